// round 3
// baseline (speedup 1.0000x reference)
#include <cuda_runtime.h>
#include <math.h>

#define TWO_N 8192
#define NHALF 4096
#define D 256
#define TILE 64
#define NBLK (TWO_N / TILE)   // 128 blocks

// Scratch (no allocations allowed): normalized reps + per-block partial losses
__device__ float d_reps[TWO_N * D];      // 8 MB, L2-resident during GEMM
__device__ float d_partial[NBLK];

// ---------------------------------------------------------------------------
// Kernel 1: L2-normalize rows of [emb_i; emb_j] into d_reps. One block per row.
// ---------------------------------------------------------------------------
__global__ void __launch_bounds__(256) normalize_kernel(
    const float* __restrict__ emb_i, const float* __restrict__ emb_j)
{
    int row = blockIdx.x;
    int tid = threadIdx.x;   // 0..255 == d index
    const float* src = (row < NHALF) ? (emb_i + (size_t)row * D)
                                     : (emb_j + (size_t)(row - NHALF) * D);
    float x = src[tid];
    float sq = x * x;
    #pragma unroll
    for (int o = 16; o; o >>= 1) sq += __shfl_xor_sync(0xffffffffu, sq, o);
    __shared__ float ws[8];
    if ((tid & 31) == 0) ws[tid >> 5] = sq;
    __syncthreads();
    float tot = 0.f;
    #pragma unroll
    for (int w = 0; w < 8; w++) tot += ws[w];
    float inv = 1.0f / fmaxf(sqrtf(tot), 1e-12f);
    d_reps[(size_t)row * D + tid] = x * inv;
}

// ---------------------------------------------------------------------------
// Kernel 2: fused Gram-tile + exp-sum. Each block owns 64 rows, streams all
// 8192 columns in 64-wide tiles. 16x16 threads, 4x4 micro-tile per thread.
// Shared layout:
//   As : 64 rows x 260 floats (pad 4 -> conflict-free dual-broadcast reads)
//   Bt : 256 d   x 68  floats (transposed B tile; float4 read per d is a
//                              contiguous 256B warp access -> conflict-free)
// ---------------------------------------------------------------------------
#define AS_STRIDE 260
#define BT_STRIDE 68
#define SMEM_FLOATS (TILE * AS_STRIDE + D * BT_STRIDE + TILE)

__global__ void __launch_bounds__(256, 1) loss_kernel()
{
    extern __shared__ float sm[];
    float* As     = sm;                            // 64*260
    float* Bt     = sm + TILE * AS_STRIDE;         // 256*68
    float* posArr = Bt + D * BT_STRIDE;            // 64

    int tid = threadIdx.x;
    int tx = tid & 15;
    int ty = tid >> 4;
    int r0 = ty * 4;          // local row base
    int c0 = tx * 4;          // local col base
    int rbase = blockIdx.x * TILE;

    // Load this block's 64 A-rows once (coalesced)
    for (int idx = tid; idx < TILE * D; idx += 256) {
        int r = idx >> 8, d = idx & 255;
        As[r * AS_STRIDE + d] = d_reps[(size_t)(rbase + r) * D + d];
    }
    if (tid < TILE) posArr[tid] = 0.f;

    float rowsum[4] = {0.f, 0.f, 0.f, 0.f};

    for (int ct = 0; ct < NBLK; ct++) {
        int cbase = ct * TILE;
        __syncthreads();    // previous tile's Bt reads done
        // Load B tile transposed: Bt[d][c]
        for (int idx = tid; idx < TILE * D; idx += 256) {
            int c = idx >> 8, d = idx & 255;
            Bt[d * BT_STRIDE + c] = d_reps[(size_t)(cbase + c) * D + d];
        }
        __syncthreads();

        float acc[4][4] = {};
        #pragma unroll 4
        for (int d = 0; d < D; d++) {
            float4 b = *reinterpret_cast<const float4*>(&Bt[d * BT_STRIDE + c0]);
            float a0 = As[(r0 + 0) * AS_STRIDE + d];
            float a1 = As[(r0 + 1) * AS_STRIDE + d];
            float a2 = As[(r0 + 2) * AS_STRIDE + d];
            float a3 = As[(r0 + 3) * AS_STRIDE + d];
            acc[0][0] += a0 * b.x; acc[0][1] += a0 * b.y; acc[0][2] += a0 * b.z; acc[0][3] += a0 * b.w;
            acc[1][0] += a1 * b.x; acc[1][1] += a1 * b.y; acc[1][2] += a1 * b.z; acc[1][3] += a1 * b.w;
            acc[2][0] += a2 * b.x; acc[2][1] += a2 * b.y; acc[2][2] += a2 * b.z; acc[2][3] += a2 * b.w;
            acc[3][0] += a3 * b.x; acc[3][1] += a3 * b.y; acc[3][2] += a3 * b.z; acc[3][3] += a3 * b.w;
        }

        // Consume tile: logits in [-2,2] -> exp is overflow-safe, no max pass.
        #pragma unroll
        for (int i = 0; i < 4; i++) {
            int r = rbase + r0 + i;
            int posc = (r + NHALF) & (TWO_N - 1);
            #pragma unroll
            for (int j = 0; j < 4; j++) {
                int c = cbase + c0 + j;
                float s = 2.0f * acc[i][j];      // /TEMPERATURE (=0.5)
                if (c == posc) posArr[r0 + i] = s;
                if (c != r)    rowsum[i] += __expf(s);
            }
        }
    }

    // Reduce rowsum across the 16 tx threads sharing each row (reuse As space)
    __syncthreads();
    float* red = As;   // 64*16 floats needed, As is free now
    #pragma unroll
    for (int i = 0; i < 4; i++) red[(r0 + i) * 16 + tx] = rowsum[i];
    __syncthreads();

    // 64 threads finish 64 rows: loss_r = log(sum_r) - pos_r ; stash in Bt[0..63]
    if (tid < TILE) {
        float s = 0.f;
        #pragma unroll
        for (int k = 0; k < 16; k++) s += red[tid * 16 + k];
        Bt[tid] = logf(s) - posArr[tid];
    }
    __syncthreads();
    if (tid == 0) {
        float t = 0.f;
        #pragma unroll
        for (int r = 0; r < TILE; r++) t += Bt[r];
        d_partial[blockIdx.x] = t;
    }
}

// ---------------------------------------------------------------------------
// Kernel 3: deterministic final reduction of 128 partials -> mean
// ---------------------------------------------------------------------------
__global__ void __launch_bounds__(128) finalize_kernel(float* __restrict__ out)
{
    int tid = threadIdx.x;
    float v = d_partial[tid];
    #pragma unroll
    for (int o = 16; o; o >>= 1) v += __shfl_xor_sync(0xffffffffu, v, o);
    __shared__ float w[4];
    if ((tid & 31) == 0) w[tid >> 5] = v;
    __syncthreads();
    if (tid == 0) out[0] = (w[0] + w[1] + w[2] + w[3]) * (1.0f / (float)TWO_N);
}

// ---------------------------------------------------------------------------
extern "C" void kernel_launch(void* const* d_in, const int* in_sizes, int n_in,
                              void* d_out, int out_size)
{
    (void)in_sizes; (void)n_in; (void)out_size;
    const float* emb_i = (const float*)d_in[0];
    const float* emb_j = (const float*)d_in[1];
    float* out = (float*)d_out;

    static const size_t smem_bytes = SMEM_FLOATS * sizeof(float);  // ~136.5 KB
    cudaFuncSetAttribute(loss_kernel,
                         cudaFuncAttributeMaxDynamicSharedMemorySize,
                         (int)smem_bytes);

    normalize_kernel<<<TWO_N, 256>>>(emb_i, emb_j);
    loss_kernel<<<NBLK, 256, smem_bytes>>>();
    finalize_kernel<<<1, 128>>>(out);
}

// round 13
// speedup vs baseline: 10.7125x; 10.7125x over previous
#include <cuda_runtime.h>
#include <cuda_bf16.h>
#include <math.h>
#include <stdint.h>

#define TWO_N 8192
#define NHALF 4096
#define D 256
#define MTILE 128
#define NTILE 128
#define COLS_PER_CTA 4096
#define NT (COLS_PER_CTA / NTILE)   // 32
#define NROWBLK (TWO_N / MTILE)     // 64
#define NCOLHALF 2

// Padded smem row: 256 bf16 data + 8 pad = 264 bf16 = 528 B (33 16B-banks:
// consecutive rows land on consecutive banks -> ldmatrix conflict-free)
#define ROWB 528

__device__ __align__(16) __nv_bfloat16 d_reps_bf16[TWO_N * D];   // 4 MB
__device__ float d_rowsum[NCOLHALF][TWO_N];
__device__ float d_rowpos[NCOLHALF][TWO_N];

// ---------------- smem / async helpers ----------------
__device__ __forceinline__ uint32_t smem_u32(const void* p) {
    uint32_t a;
    asm("{ .reg .u64 t; cvta.to.shared.u64 t, %1; cvt.u32.u64 %0, t; }" : "=r"(a) : "l"(p));
    return a;
}
__device__ __forceinline__ void cp_async16(uint32_t dst, const void* src) {
    asm volatile("cp.async.cg.shared.global [%0], [%1], 16;" :: "r"(dst), "l"(src) : "memory");
}
#define CP_COMMIT() asm volatile("cp.async.commit_group;" ::: "memory")
#define CP_WAIT0()  asm volatile("cp.async.wait_group 0;" ::: "memory")

__device__ __forceinline__ void ldsm_x4(uint32_t* r, uint32_t addr) {
    asm volatile("ldmatrix.sync.aligned.m8n8.x4.shared.b16 {%0,%1,%2,%3}, [%4];"
        : "=r"(r[0]), "=r"(r[1]), "=r"(r[2]), "=r"(r[3]) : "r"(addr));
}
__device__ __forceinline__ void ldsm_x2(uint32_t* r, uint32_t addr) {
    asm volatile("ldmatrix.sync.aligned.m8n8.x2.shared.b16 {%0,%1}, [%2];"
        : "=r"(r[0]), "=r"(r[1]) : "r"(addr));
}
__device__ __forceinline__ void mma_bf16(float* c, const uint32_t* a, const uint32_t* b) {
    asm volatile("mma.sync.aligned.m16n8k16.row.col.f32.bf16.bf16.f32 "
        "{%0,%1,%2,%3}, {%4,%5,%6,%7}, {%8,%9}, {%0,%1,%2,%3};"
        : "+f"(c[0]), "+f"(c[1]), "+f"(c[2]), "+f"(c[3])
        : "r"(a[0]), "r"(a[1]), "r"(a[2]), "r"(a[3]), "r"(b[0]), "r"(b[1]));
}

// ---------------- SMEM layout (bytes) ----------------
#define SMEM_A   0
#define SMEM_B0  (MTILE * ROWB)            // 67584
#define SMEM_B1  (2 * MTILE * ROWB)        // 135168
#define SMEM_BYTES (3 * MTILE * ROWB)      // 202752

// Load one 128-row x 256-col bf16 tile (row-major, 512B/row) into padded smem.
__device__ __forceinline__ void load_tile(uint32_t dst, const __nv_bfloat16* g, int tid) {
    const char* gc = (const char*)g;
    #pragma unroll
    for (int i = 0; i < 16; i++) {
        int ch = tid + i * 256;            // 4096 chunks of 16B
        int row = ch >> 5, kc = ch & 31;
        cp_async16(dst + row * ROWB + kc * 16, gc + (size_t)row * 512 + kc * 16);
    }
}

// ---------------------------------------------------------------------------
// Kernel 1: L2-normalize -> bf16 reps. One warp per row.
// ---------------------------------------------------------------------------
__global__ void __launch_bounds__(256) normalize_kernel(
    const float* __restrict__ emb_i, const float* __restrict__ emb_j)
{
    int warp = threadIdx.x >> 5, lane = threadIdx.x & 31;
    int row = blockIdx.x * 8 + warp;
    const float* src = (row < NHALF) ? (emb_i + (size_t)row * D)
                                     : (emb_j + (size_t)(row - NHALF) * D);
    float4 v0 = *reinterpret_cast<const float4*>(src + lane * 4);
    float4 v1 = *reinterpret_cast<const float4*>(src + 128 + lane * 4);
    float sq = v0.x*v0.x + v0.y*v0.y + v0.z*v0.z + v0.w*v0.w
             + v1.x*v1.x + v1.y*v1.y + v1.z*v1.z + v1.w*v1.w;
    #pragma unroll
    for (int o = 16; o; o >>= 1) sq += __shfl_xor_sync(0xffffffffu, sq, o);
    float inv = 1.0f / fmaxf(sqrtf(sq), 1e-12f);

    __nv_bfloat162 a = __floats2bfloat162_rn(v0.x * inv, v0.y * inv);
    __nv_bfloat162 b = __floats2bfloat162_rn(v0.z * inv, v0.w * inv);
    __nv_bfloat162 c = __floats2bfloat162_rn(v1.x * inv, v1.y * inv);
    __nv_bfloat162 d = __floats2bfloat162_rn(v1.z * inv, v1.w * inv);
    uint2* dst = reinterpret_cast<uint2*>(d_reps_bf16 + (size_t)row * D);
    uint2 p0; p0.x = *(uint32_t*)&a; p0.y = *(uint32_t*)&b;
    uint2 p1; p1.x = *(uint32_t*)&c; p1.y = *(uint32_t*)&d;
    dst[lane] = p0;
    dst[32 + lane] = p1;
}

// ---------------------------------------------------------------------------
// Kernel 2: bf16 mma.sync Gram tiles + fused exp-sum epilogue.
// grid = (64 rowblocks, 2 col halves) = 128 CTAs, 256 threads (8 warps, 2x4).
// Each warp computes a 64x32 sub-tile of the 128x128 output via m16n8k16.
// B tiles double-buffered with cp.async prefetch overlapping compute.
// ---------------------------------------------------------------------------
__global__ void __launch_bounds__(256, 1) loss_kernel()
{
    extern __shared__ char smem[];
    const uint32_t sb = smem_u32(smem);
    const int tid  = threadIdx.x;
    const int wid  = tid >> 5, lane = tid & 31;
    const int wm   = wid >> 2;            // 0..1 : row block of 64
    const int wn   = wid & 3;             // 0..3 : col block of 32
    const int rbase = blockIdx.x * MTILE;
    const int colhalf = blockIdx.y;
    const int cbase = colhalf * COLS_PER_CTA;

    // ---- prologue: A + B tile 0 ----
    load_tile(sb + SMEM_A,  d_reps_bf16 + (size_t)rbase * D, tid);
    load_tile(sb + SMEM_B0, d_reps_bf16 + (size_t)cbase * D, tid);
    CP_COMMIT(); CP_WAIT0();
    __syncthreads();

    // ldmatrix base addresses (k-step adds k*32 bytes)
    // A frag i (m16k16): rows wm*64+i*16 + (lane&15), k-half (lane>>4)
    uint32_t addrA[4];
    #pragma unroll
    for (int i = 0; i < 4; i++)
        addrA[i] = sb + SMEM_A + (uint32_t)(wm * 64 + i * 16 + (lane & 15)) * ROWB
                 + (uint32_t)(lane >> 4) * 16;
    // B frag j (n8k16): rows wn*32+j*8 + (lane&7), k-half ((lane>>3)&1)
    uint32_t addrBoff[4];
    #pragma unroll
    for (int j = 0; j < 4; j++)
        addrBoff[j] = (uint32_t)(wn * 32 + j * 8 + (lane & 7)) * ROWB
                    + (uint32_t)((lane >> 3) & 1) * 16;

    // per-thread row-sum state (accumulated across all tiles)
    float sumLo[4] = {}, sumHi[4] = {}, posLo[4] = {}, posHi[4] = {};
    int rLo[4], pLo[4], pHi[4];
    #pragma unroll
    for (int i = 0; i < 4; i++) {
        rLo[i] = rbase + wm * 64 + i * 16 + (lane >> 2);
        pLo[i] = (rLo[i] + NHALF) & (TWO_N - 1);
        pHi[i] = (rLo[i] + 8 + NHALF) & (TWO_N - 1);
    }

    for (int t = 0; t < NT; t++) {
        const uint32_t bB = sb + ((t & 1) ? SMEM_B1 : SMEM_B0);
        // prefetch next B tile into the other buffer (overlaps compute)
        if (t + 1 < NT)
            load_tile(sb + (((t + 1) & 1) ? SMEM_B1 : SMEM_B0),
                      d_reps_bf16 + (size_t)(cbase + (t + 1) * NTILE) * D, tid);
        CP_COMMIT();

        float acc[4][4][4] = {};
        #pragma unroll
        for (int k = 0; k < 16; k++) {
            uint32_t a[4][4], b[4][2];
            #pragma unroll
            for (int i = 0; i < 4; i++) ldsm_x4(a[i], addrA[i] + k * 32);
            #pragma unroll
            for (int j = 0; j < 4; j++) ldsm_x2(b[j], bB + addrBoff[j] + k * 32);
            #pragma unroll
            for (int i = 0; i < 4; i++)
                #pragma unroll
                for (int j = 0; j < 4; j++)
                    mma_bf16(acc[i][j], a[i], b[j]);
        }

        // ---- fused epilogue: logits = 2*dot; exp-sum excl. diag; grab pos ----
        const int cb = cbase + t * NTILE + wn * 32 + (lane & 3) * 2;
        #pragma unroll
        for (int i = 0; i < 4; i++) {
            const int rl = rLo[i], rh = rl + 8;
            #pragma unroll
            for (int j = 0; j < 4; j++) {
                const int c0 = cb + j * 8, c1 = c0 + 1;
                float s00 = 2.0f * acc[i][j][0];   // (rl, c0)
                float s01 = 2.0f * acc[i][j][1];   // (rl, c1)
                float s10 = 2.0f * acc[i][j][2];   // (rh, c0)
                float s11 = 2.0f * acc[i][j][3];   // (rh, c1)
                sumLo[i] += (c0 != rl ? __expf(s00) : 0.f)
                          + (c1 != rl ? __expf(s01) : 0.f);
                sumHi[i] += (c0 != rh ? __expf(s10) : 0.f)
                          + (c1 != rh ? __expf(s11) : 0.f);
                posLo[i] += (c0 == pLo[i] ? s00 : 0.f) + (c1 == pLo[i] ? s01 : 0.f);
                posHi[i] += (c0 == pHi[i] ? s10 : 0.f) + (c1 == pHi[i] ? s11 : 0.f);
            }
        }

        CP_WAIT0();
        __syncthreads();   // all reads of B[t] done; next B tile resident
    }

    // ---- reduction: 4 lanes (same row) via shfl, then 4 wn warps via smem ----
    #pragma unroll
    for (int i = 0; i < 4; i++) {
        #pragma unroll
        for (int o = 1; o <= 2; o <<= 1) {
            sumLo[i] += __shfl_xor_sync(0xffffffffu, sumLo[i], o);
            sumHi[i] += __shfl_xor_sync(0xffffffffu, sumHi[i], o);
            posLo[i] += __shfl_xor_sync(0xffffffffu, posLo[i], o);
            posHi[i] += __shfl_xor_sync(0xffffffffu, posHi[i], o);
        }
    }
    float* redS = reinterpret_cast<float*>(smem);          // [128][4]
    float* redP = redS + 512;                              // [128][4]
    if ((lane & 3) == 0) {
        #pragma unroll
        for (int i = 0; i < 4; i++) {
            int rl = wm * 64 + i * 16 + (lane >> 2);
            redS[rl * 4 + wn]       = sumLo[i];
            redS[(rl + 8) * 4 + wn] = sumHi[i];
            redP[rl * 4 + wn]       = posLo[i];
            redP[(rl + 8) * 4 + wn] = posHi[i];
        }
    }
    __syncthreads();
    if (tid < MTILE) {
        float s = redS[tid*4] + redS[tid*4+1] + redS[tid*4+2] + redS[tid*4+3];
        float p = redP[tid*4] + redP[tid*4+1] + redP[tid*4+2] + redP[tid*4+3];
        d_rowsum[colhalf][rbase + tid] = s;
        d_rowpos[colhalf][rbase + tid] = p;
    }
}

// ---------------------------------------------------------------------------
// Kernel 3: deterministic final reduction -> mean loss
// ---------------------------------------------------------------------------
__global__ void __launch_bounds__(1024) finalize_kernel(float* __restrict__ out)
{
    int tid = threadIdx.x;
    float acc = 0.f;
    #pragma unroll
    for (int i = tid; i < TWO_N; i += 1024) {
        float s = d_rowsum[0][i] + d_rowsum[1][i];
        float p = d_rowpos[0][i] + d_rowpos[1][i];
        acc += logf(s) - p;
    }
    #pragma unroll
    for (int o = 16; o; o >>= 1) acc += __shfl_xor_sync(0xffffffffu, acc, o);
    __shared__ float w[32];
    if ((tid & 31) == 0) w[tid >> 5] = acc;
    __syncthreads();
    if (tid == 0) {
        float t = 0.f;
        #pragma unroll
        for (int k = 0; k < 32; k++) t += w[k];
        out[0] = t * (1.0f / (float)TWO_N);
    }
}

// ---------------------------------------------------------------------------
extern "C" void kernel_launch(void* const* d_in, const int* in_sizes, int n_in,
                              void* d_out, int out_size)
{
    (void)in_sizes; (void)n_in; (void)out_size;
    const float* emb_i = (const float*)d_in[0];
    const float* emb_j = (const float*)d_in[1];
    float* out = (float*)d_out;

    cudaFuncSetAttribute(loss_kernel,
                         cudaFuncAttributeMaxDynamicSharedMemorySize, SMEM_BYTES);

    normalize_kernel<<<TWO_N / 8, 256>>>(emb_i, emb_j);
    loss_kernel<<<dim3(NROWBLK, NCOLHALF), 256, SMEM_BYTES>>>();
    finalize_kernel<<<1, 1024>>>(out);
}

// round 17
// speedup vs baseline: 16.9395x; 1.5813x over previous
#include <cuda_runtime.h>
#include <cuda_bf16.h>
#include <math.h>
#include <stdint.h>

#define TWO_N 8192
#define NHALF 4096
#define D 256
#define MTILE 128
#define NBLK 64                 // 64 row/col blocks of 128
#define NPAIR 2080              // 64*65/2 unordered block pairs

// Padded smem row: 256 bf16 + 8 pad = 528 B (33 banks -> ldmatrix conflict-free)
#define ROWB 528

__device__ __align__(16) __nv_bfloat16 d_reps_bf16[TWO_N * D];   // 4 MB
__device__ float d_part[NBLK][TWO_N];    // 2 MB: slot-wise partial row sums
__device__ float d_rowpos[TWO_N];
__device__ float d_rowloss[TWO_N];

// ---------------- smem / async helpers ----------------
__device__ __forceinline__ uint32_t smem_u32(const void* p) {
    uint32_t a;
    asm("{ .reg .u64 t; cvta.to.shared.u64 t, %1; cvt.u32.u64 %0, t; }" : "=r"(a) : "l"(p));
    return a;
}
__device__ __forceinline__ void cp_async16(uint32_t dst, const void* src) {
    asm volatile("cp.async.cg.shared.global [%0], [%1], 16;" :: "r"(dst), "l"(src) : "memory");
}
#define CP_COMMIT() asm volatile("cp.async.commit_group;" ::: "memory")
#define CP_WAIT0()  asm volatile("cp.async.wait_group 0;" ::: "memory")

__device__ __forceinline__ void ldsm_x4(uint32_t* r, uint32_t addr) {
    asm volatile("ldmatrix.sync.aligned.m8n8.x4.shared.b16 {%0,%1,%2,%3}, [%4];"
        : "=r"(r[0]), "=r"(r[1]), "=r"(r[2]), "=r"(r[3]) : "r"(addr));
}
__device__ __forceinline__ void ldsm_x2(uint32_t* r, uint32_t addr) {
    asm volatile("ldmatrix.sync.aligned.m8n8.x2.shared.b16 {%0,%1}, [%2];"
        : "=r"(r[0]), "=r"(r[1]) : "r"(addr));
}
__device__ __forceinline__ void mma_bf16(float* c, const uint32_t* a, const uint32_t* b) {
    asm volatile("mma.sync.aligned.m16n8k16.row.col.f32.bf16.bf16.f32 "
        "{%0,%1,%2,%3}, {%4,%5,%6,%7}, {%8,%9}, {%0,%1,%2,%3};"
        : "+f"(c[0]), "+f"(c[1]), "+f"(c[2]), "+f"(c[3])
        : "r"(a[0]), "r"(a[1]), "r"(a[2]), "r"(a[3]), "r"(b[0]), "r"(b[1]));
}

// ---------------- SMEM layout (bytes) ----------------
#define SMEM_A   0
#define SMEM_B   (MTILE * ROWB)            // 67584
#define SMEM_BYTES (2 * MTILE * ROWB)      // 135168

__device__ __forceinline__ void load_tile(uint32_t dst, const __nv_bfloat16* g, int tid) {
    const char* gc = (const char*)g;
    #pragma unroll
    for (int i = 0; i < 16; i++) {
        int ch = tid + i * 256;            // 4096 chunks of 16B
        int row = ch >> 5, kc = ch & 31;
        cp_async16(dst + row * ROWB + kc * 16, gc + (size_t)row * 512 + kc * 16);
    }
}

// ---------------------------------------------------------------------------
// Kernel 1: L2-normalize -> bf16 reps. One warp per row.
// ---------------------------------------------------------------------------
__global__ void __launch_bounds__(256) normalize_kernel(
    const float* __restrict__ emb_i, const float* __restrict__ emb_j)
{
    int warp = threadIdx.x >> 5, lane = threadIdx.x & 31;
    int row = blockIdx.x * 8 + warp;
    const float* src = (row < NHALF) ? (emb_i + (size_t)row * D)
                                     : (emb_j + (size_t)(row - NHALF) * D);
    float4 v0 = *reinterpret_cast<const float4*>(src + lane * 4);
    float4 v1 = *reinterpret_cast<const float4*>(src + 128 + lane * 4);
    float sq = v0.x*v0.x + v0.y*v0.y + v0.z*v0.z + v0.w*v0.w
             + v1.x*v1.x + v1.y*v1.y + v1.z*v1.z + v1.w*v1.w;
    #pragma unroll
    for (int o = 16; o; o >>= 1) sq += __shfl_xor_sync(0xffffffffu, sq, o);
    float inv = 1.0f / fmaxf(sqrtf(sq), 1e-12f);

    __nv_bfloat162 a = __floats2bfloat162_rn(v0.x * inv, v0.y * inv);
    __nv_bfloat162 b = __floats2bfloat162_rn(v0.z * inv, v0.w * inv);
    __nv_bfloat162 c = __floats2bfloat162_rn(v1.x * inv, v1.y * inv);
    __nv_bfloat162 d = __floats2bfloat162_rn(v1.z * inv, v1.w * inv);
    uint2* dst = reinterpret_cast<uint2*>(d_reps_bf16 + (size_t)row * D);
    uint2 p0; p0.x = *(uint32_t*)&a; p0.y = *(uint32_t*)&b;
    uint2 p1; p1.x = *(uint32_t*)&c; p1.y = *(uint32_t*)&d;
    dst[lane] = p0;
    dst[32 + lane] = p1;
}

// ---------------------------------------------------------------------------
// Kernel 2: symmetric Gram pairs. CTA p computes block pair (I,J), I<=J:
// S = A_I * A_J^T (128x128). exp(2*S) feeds row sums of block I (row dir)
// and, for I<J, row sums of block J (col dir, symmetry). Block diagonal of
// pairs (I, I+32) = positive logits for BOTH paired rows. 2080 CTAs.
// ---------------------------------------------------------------------------
__global__ void __launch_bounds__(256, 1) loss_kernel()
{
    // ---- decode flat pair index -> (I, J) ----
    int I = 0, rem = blockIdx.x;
    while (rem >= NBLK - I) { rem -= NBLK - I; I++; }
    const int J = I + rem;
    const bool offdiag = (I != J);

    extern __shared__ char smem[];
    const uint32_t sb = smem_u32(smem);
    const int tid  = threadIdx.x;
    const int wid  = tid >> 5, lane = tid & 31;
    const int wm   = wid >> 2;            // 0..1 : row block of 64
    const int wn   = wid & 3;             // 0..3 : col block of 32
    const int rbase = I * MTILE;
    const int cbase = J * MTILE;

    // ---- load both blocks ----
    load_tile(sb + SMEM_A, d_reps_bf16 + (size_t)rbase * D, tid);
    load_tile(sb + SMEM_B, d_reps_bf16 + (size_t)cbase * D, tid);
    CP_COMMIT(); CP_WAIT0();
    __syncthreads();

    uint32_t addrA[4];
    #pragma unroll
    for (int i = 0; i < 4; i++)
        addrA[i] = sb + SMEM_A + (uint32_t)(wm * 64 + i * 16 + (lane & 15)) * ROWB
                 + (uint32_t)(lane >> 4) * 16;
    uint32_t addrB[4];
    #pragma unroll
    for (int j = 0; j < 4; j++)
        addrB[j] = sb + SMEM_B + (uint32_t)(wn * 32 + j * 8 + (lane & 7)) * ROWB
                 + (uint32_t)((lane >> 3) & 1) * 16;

    float acc[4][4][4] = {};
    #pragma unroll
    for (int k = 0; k < 16; k++) {
        uint32_t a[4][4], b[4][2];
        #pragma unroll
        for (int i = 0; i < 4; i++) ldsm_x4(a[i], addrA[i] + k * 32);
        #pragma unroll
        for (int j = 0; j < 4; j++) ldsm_x2(b[j], addrB[j] + k * 32);
        #pragma unroll
        for (int i = 0; i < 4; i++)
            #pragma unroll
            for (int j = 0; j < 4; j++)
                mma_bf16(acc[i][j], a[i], b[j]);
    }

    // ---- fused epilogue: exp once, row-sums + col-sums + pos ----
    float sumLo[4] = {}, sumHi[4] = {};     // row-direction partials
    float colsum[4][2] = {};                // col-direction partials (c0,c1 per j)
    const int cb = cbase + wn * 32 + (lane & 3) * 2;
    #pragma unroll
    for (int i = 0; i < 4; i++) {
        const int rl = rbase + wm * 64 + i * 16 + (lane >> 2);
        const int rh = rl + 8;
        const int pLo = (rl + NHALF) & (TWO_N - 1);
        const int pHi = (rh + NHALF) & (TWO_N - 1);
        #pragma unroll
        for (int j = 0; j < 4; j++) {
            const int c0 = cb + j * 8, c1 = c0 + 1;
            float s00 = 2.0f * acc[i][j][0];   // (rl, c0)
            float s01 = 2.0f * acc[i][j][1];   // (rl, c1)
            float s10 = 2.0f * acc[i][j][2];   // (rh, c0)
            float s11 = 2.0f * acc[i][j][3];   // (rh, c1)
            float e00 = __expf(s00), e01 = __expf(s01);
            float e10 = __expf(s10), e11 = __expf(s11);
            sumLo[i] += (c0 != rl ? e00 : 0.f) + (c1 != rl ? e01 : 0.f);
            sumHi[i] += (c0 != rh ? e10 : 0.f) + (c1 != rh ? e11 : 0.f);
            colsum[j][0] += e00 + e10;
            colsum[j][1] += e01 + e11;
            // positive logits: block diagonal of pairs (I, I+32); symmetric,
            // single writer per row across the whole grid.
            if (c0 == pLo) { d_rowpos[rl] = s00; d_rowpos[c0] = s00; }
            if (c1 == pLo) { d_rowpos[rl] = s01; d_rowpos[c1] = s01; }
            if (c0 == pHi) { d_rowpos[rh] = s10; d_rowpos[c0] = s10; }
            if (c1 == pHi) { d_rowpos[rh] = s11; d_rowpos[c1] = s11; }
        }
    }

    // ---- row-sum reduction: 4 lanes/row via shfl, then 4 wn warps via smem ----
    #pragma unroll
    for (int i = 0; i < 4; i++) {
        #pragma unroll
        for (int o = 1; o <= 2; o <<= 1) {
            sumLo[i] += __shfl_xor_sync(0xffffffffu, sumLo[i], o);
            sumHi[i] += __shfl_xor_sync(0xffffffffu, sumHi[i], o);
        }
    }
    __syncthreads();                       // smem A/B free now
    float* redS = reinterpret_cast<float*>(smem);          // [128][4]
    float* redC = redS + 512;                              // [2][128]
    if ((lane & 3) == 0) {
        #pragma unroll
        for (int i = 0; i < 4; i++) {
            int rl = wm * 64 + i * 16 + (lane >> 2);
            redS[rl * 4 + wn]       = sumLo[i];
            redS[(rl + 8) * 4 + wn] = sumHi[i];
        }
    }

    // ---- col-sum reduction: 8 row-groups via shfl, then 2 wm warps via smem ----
    #pragma unroll
    for (int j = 0; j < 4; j++) {
        #pragma unroll
        for (int o = 4; o <= 16; o <<= 1) {
            colsum[j][0] += __shfl_xor_sync(0xffffffffu, colsum[j][0], o);
            colsum[j][1] += __shfl_xor_sync(0xffffffffu, colsum[j][1], o);
        }
    }
    if (lane < 4) {
        #pragma unroll
        for (int j = 0; j < 4; j++) {
            int col = wn * 32 + lane * 2 + j * 8;
            redC[wm * 128 + col]     = colsum[j][0];
            redC[wm * 128 + col + 1] = colsum[j][1];
        }
    }
    __syncthreads();

    // slot layout: rowblock I row-part -> slot J; rowblock J col-part -> slot I.
    if (tid < MTILE) {
        float s = redS[tid*4] + redS[tid*4+1] + redS[tid*4+2] + redS[tid*4+3];
        d_part[J][rbase + tid] = s;
        if (offdiag)
            d_part[I][cbase + tid] = redC[tid] + redC[128 + tid];
    }
}

// ---------------------------------------------------------------------------
// Kernel 3: per-row reduction over 64 slots -> per-row loss
// ---------------------------------------------------------------------------
__global__ void __launch_bounds__(1024) rowreduce_kernel()
{
    int r = blockIdx.x * 1024 + threadIdx.x;
    float s = 0.f;
    #pragma unroll 8
    for (int k = 0; k < NBLK; k++) s += d_part[k][r];
    d_rowloss[r] = logf(s) - d_rowpos[r];
}

// ---------------------------------------------------------------------------
// Kernel 4: deterministic final reduction -> mean
// ---------------------------------------------------------------------------
__global__ void __launch_bounds__(1024) finalize_kernel(float* __restrict__ out)
{
    int tid = threadIdx.x;
    float acc = 0.f;
    #pragma unroll
    for (int i = tid; i < TWO_N; i += 1024) acc += d_rowloss[i];
    #pragma unroll
    for (int o = 16; o; o >>= 1) acc += __shfl_xor_sync(0xffffffffu, acc, o);
    __shared__ float w[32];
    if ((tid & 31) == 0) w[tid >> 5] = acc;
    __syncthreads();
    if (tid == 0) {
        float t = 0.f;
        #pragma unroll
        for (int k = 0; k < 32; k++) t += w[k];
        out[0] = t * (1.0f / (float)TWO_N);
    }
}

// ---------------------------------------------------------------------------
extern "C" void kernel_launch(void* const* d_in, const int* in_sizes, int n_in,
                              void* d_out, int out_size)
{
    (void)in_sizes; (void)n_in; (void)out_size;
    const float* emb_i = (const float*)d_in[0];
    const float* emb_j = (const float*)d_in[1];
    float* out = (float*)d_out;

    cudaFuncSetAttribute(loss_kernel,
                         cudaFuncAttributeMaxDynamicSharedMemorySize, SMEM_BYTES);

    normalize_kernel<<<TWO_N / 8, 256>>>(emb_i, emb_j);
    loss_kernel<<<NPAIR, 256, SMEM_BYTES>>>();
    rowreduce_kernel<<<TWO_N / 1024, 1024>>>();
    finalize_kernel<<<1, 1024>>>(out);
}